// round 11
// baseline (speedup 1.0000x reference)
#include <cuda_runtime.h>

// Problem constants (fixed by the reference: x,y are [8192, 1024] fp32)
#define N_ROWS 8192
#define D      1024
#define WARPS_PER_BLOCK 8
#define GRID 512                       // single wave: < 592 concurrent CTAs
#define ROWS_PER_WARP 2                // 512 * 8 * 2 = 8192 rows
#define BLOCK_THREADS (WARPS_PER_BLOCK * 32)   // 256

// Per-block partial sums; every slot rewritten each call before being read.
__device__ float g_partials[GRID];
// Arrival counter, reset by the last block each call -> graph-replay safe.
__device__ unsigned int g_counter = 0;

// Roofline note (rounds 1-10): LDG.128, 1 row/warp loop, 256-thread blocks,
// 32 regs, ~84% occ sustains ~6.0 TB/s = the path-independent LTS chip cap.
// Wider loads, more warps, more regs, evict_last, and TMA pipelines all
// regressed or tied. This round removes the only remaining modeled cost:
// the 2-wave launch (1024 CTAs vs 592 concurrent) -> 512 CTAs, 2 rows/warp.
__global__ __launch_bounds__(BLOCK_THREADS)
void row_loss_fused_kernel(const float* __restrict__ x,
                           const float* __restrict__ y,
                           float* __restrict__ out) {
    const int warp = threadIdx.x >> 5;
    const int lane = threadIdx.x & 31;

    float loss_sum = 0.0f;  // meaningful on lane 0 only

    #pragma unroll
    for (int rr = 0; rr < ROWS_PER_WARP; rr++) {
        // Row assignment: first 4096 rows in pass 0, second 4096 in pass 1.
        const int row = (blockIdx.x * WARPS_PER_BLOCK + warp) + rr * (GRID * WARPS_PER_BLOCK);

        const float4* __restrict__ xr =
            reinterpret_cast<const float4*>(x + (size_t)row * D);
        const float4* __restrict__ yr =
            reinterpret_cast<const float4*>(y + (size_t)row * D);

        float dot = 0.0f, xx = 0.0f, yy = 0.0f;

        // 1024 floats/row = 256 float4. Lane l reads float4 l, l+32, ...
        // -> contiguous 512B warp bursts (proven-best R2 pattern).
        #pragma unroll
        for (int k = 0; k < 8; k++) {
            float4 a = xr[lane + 32 * k];
            float4 b = yr[lane + 32 * k];
            dot += a.x * b.x + a.y * b.y + a.z * b.z + a.w * b.w;
            xx  += a.x * a.x + a.y * a.y + a.z * a.z + a.w * a.w;
            yy  += b.x * b.x + b.y * b.y + b.z * b.z + b.w * b.w;
        }

        #pragma unroll
        for (int off = 16; off > 0; off >>= 1) {
            dot += __shfl_down_sync(0xFFFFFFFFu, dot, off);
            xx  += __shfl_down_sync(0xFFFFFFFFu, xx,  off);
            yy  += __shfl_down_sync(0xFFFFFFFFu, yy,  off);
        }

        if (lane == 0) {
            float inv_norm = rsqrtf(fmaxf(xx * yy, 1e-24f));
            float cosv = dot * inv_norm;
            float arg  = fmaxf((cosv + 1.0f) * 0.5f, 1e-30f);
            loss_sum += -logf(arg);
        }
    }

    __shared__ float s_loss[WARPS_PER_BLOCK];
    if (lane == 0) s_loss[warp] = loss_sum;
    __syncthreads();

    __shared__ bool s_is_last;
    if (threadIdx.x == 0) {
        float t = 0.0f;
        #pragma unroll
        for (int i = 0; i < WARPS_PER_BLOCK; i++) t += s_loss[i];
        g_partials[blockIdx.x] = t;
        __threadfence();
        unsigned int prev = atomicAdd(&g_counter, 1u);
        s_is_last = (prev == (unsigned int)(GRID - 1));
    }
    __syncthreads();

    // Single last-arriving block: deterministic fixed-order reduction of all
    // partials; re-arms the counter for the next graph replay.
    if (s_is_last) {
        float v = 0.0f;
        #pragma unroll
        for (int i = 0; i < GRID / BLOCK_THREADS; i++)
            v += g_partials[threadIdx.x + i * BLOCK_THREADS];

        #pragma unroll
        for (int off = 16; off > 0; off >>= 1)
            v += __shfl_down_sync(0xFFFFFFFFu, v, off);

        __shared__ float s_fin[WARPS_PER_BLOCK];
        if (lane == 0) s_fin[warp] = v;
        __syncthreads();

        if (threadIdx.x == 0) {
            float t = 0.0f;
            #pragma unroll
            for (int i = 0; i < WARPS_PER_BLOCK; i++) t += s_fin[i];
            out[0] = t * (1.0f / (float)N_ROWS);
            g_counter = 0;  // re-arm for next graph replay
        }
    }
}

extern "C" void kernel_launch(void* const* d_in, const int* in_sizes, int n_in,
                              void* d_out, int out_size) {
    const float* x = (const float*)d_in[0];
    const float* y = (const float*)d_in[1];
    float* out = (float*)d_out;

    row_loss_fused_kernel<<<GRID, BLOCK_THREADS>>>(x, y, out);
}